// round 15
// baseline (speedup 1.0000x reference)
#include <cuda_runtime.h>
#include <cuda_fp16.h>
#include <cstdint>

// Problem constants: B=2, S=2048, D=1024, H=16, HD=64
#define BB   2
#define SS   2048
#define DD   1024
#define HH   16
#define HD   64
#define MDIM (BB*SS)     // 4096
#define KD   DD          // 1024
#define KW   (KD/2)      // 512 fp16x2 words per row
#define HDW  (HD/2)      // 32 words per head row

// Scratch (allocation-free rule). fp16x2 packed words, plain layouts.
__device__ uint32_t g_x16[MDIM*KW];
__device__ uint32_t g_w16[4][DD*KW];          // qw,kw,vw,ow
__device__ uint32_t g_q16[BB*HH*SS*HDW];      // [B,H,S,HD] (q pre-scaled by 0.125*log2e)
__device__ uint32_t g_k16[BB*HH*SS*HDW];
__device__ uint32_t g_v16[BB*HH*SS*HDW];
__device__ uint32_t g_attn16[BB*SS*DD/2];     // [B,S,D]

// ---------------------------------------------------------------------------
// helpers
// ---------------------------------------------------------------------------
__device__ __forceinline__ uint32_t packh2(float lo, float hi) {
    uint32_t r;
    asm("cvt.rn.f16x2.f32 %0, %1, %2;" : "=r"(r) : "f"(hi), "f"(lo));
    return r;   // low half = lo
}
__device__ __forceinline__ uint32_t hex22(uint32_t a) {
    uint32_t r; asm("ex2.approx.f16x2 %0,%1;" : "=r"(r) : "r"(a)); return r;
}

// fp32-accum MMA (PV + projections)
__device__ __forceinline__ void mma_f16(float* c, const uint32_t* a, const uint32_t* b) {
    asm volatile(
        "mma.sync.aligned.m16n8k16.row.col.f32.f16.f16.f32 "
        "{%0,%1,%2,%3}, {%4,%5,%6,%7}, {%8,%9}, {%0,%1,%2,%3};"
        : "+f"(c[0]), "+f"(c[1]), "+f"(c[2]), "+f"(c[3])
        : "r"(a[0]), "r"(a[1]), "r"(a[2]), "r"(a[3]),
          "r"(b[0]), "r"(b[1]));
}
// fp16-accum MMA (QK scores): C fragment = 2 packed h2 regs {c0,c1},{c2,c3}
__device__ __forceinline__ void mma_f16h(uint32_t* ch, const uint32_t* a, const uint32_t* b) {
    asm volatile(
        "mma.sync.aligned.m16n8k16.row.col.f16.f16.f16.f16 "
        "{%0,%1}, {%2,%3,%4,%5}, {%6,%7}, {%0,%1};"
        : "+r"(ch[0]), "+r"(ch[1])
        : "r"(a[0]), "r"(a[1]), "r"(a[2]), "r"(a[3]),
          "r"(b[0]), "r"(b[1]));
}

__device__ __forceinline__ void ldsm4(uint32_t addr, uint32_t& r0, uint32_t& r1,
                                      uint32_t& r2, uint32_t& r3) {
    asm volatile("ldmatrix.sync.aligned.m8n8.x4.shared.b16 {%0,%1,%2,%3}, [%4];"
                 : "=r"(r0), "=r"(r1), "=r"(r2), "=r"(r3) : "r"(addr));
}
__device__ __forceinline__ void ldsm4t(uint32_t addr, uint32_t& r0, uint32_t& r1,
                                       uint32_t& r2, uint32_t& r3) {
    asm volatile("ldmatrix.sync.aligned.m8n8.x4.trans.shared.b16 {%0,%1,%2,%3}, [%4];"
                 : "=r"(r0), "=r"(r1), "=r"(r2), "=r"(r3) : "r"(addr));
}

__device__ __forceinline__ void cpa16s(uint32_t saddr, const void* g) {
    asm volatile("cp.async.cg.shared.global [%0], [%1], 16;" :: "r"(saddr), "l"(g) : "memory");
}

__device__ __forceinline__ uint32_t smem_u32(const void* p) {
    uint32_t a;
    asm("{ .reg .u64 t; cvta.to.shared.u64 t, %1; cvt.u32.u64 %0, t; }" : "=r"(a) : "l"(p));
    return a;
}

// swizzled byte address of 16B chunk (row: 128B pitch, chunk 0..7)
__device__ __forceinline__ uint32_t sw_addr(uint32_t base, int row, int chunk) {
    return base + (uint32_t)(row * 128 + ((chunk ^ (row & 7)) << 4));
}

// ---------------------------------------------------------------------------
// prep: fp32 -> fp16x2 words. 8192 rows x 512 words (x then qw,kw,vw,ow).
// ---------------------------------------------------------------------------
__global__ void __launch_bounds__(256) prep_f16(const float* __restrict__ x,
                                                const float* __restrict__ qw,
                                                const float* __restrict__ kw,
                                                const float* __restrict__ vw,
                                                const float* __restrict__ ow)
{
    const int idx = blockIdx.x * 256 + threadIdx.x;
    const int row = idx >> 7;
    const int q8  = (idx & 127) << 3;

    const float* src;
    uint32_t*    dst;
    if (row < MDIM) {
        src = x + (size_t)row * KD;
        dst = g_x16 + (size_t)row * KW;
    } else {
        const int w = (row - MDIM) >> 10;
        const int r = (row - MDIM) & 1023;
        const float* ws = (w == 0) ? qw : (w == 1) ? kw : (w == 2) ? vw : ow;
        src = ws + (size_t)r * KD;
        dst = g_w16[w] + (size_t)r * KW;
    }
    float4 f0 = *(const float4*)(src + q8);
    float4 f1 = *(const float4*)(src + q8 + 4);
    uint4 o;
    o.x = packh2(f0.x, f0.y); o.y = packh2(f0.z, f0.w);
    o.z = packh2(f1.x, f1.y); o.w = packh2(f1.z, f1.w);
    *(uint4*)(dst + (q8 >> 1)) = o;
}

// ---------------------------------------------------------------------------
// FP16 tensor-core GEMM (proven config): C = A @ W^T + bias.
// CTA 128x128, 256 thr (8 warps: 4m x 2n, warp tile 32x64).
// BK=64 halves/stage (128B rows, XOR-swizzled), 3-stage cp.async.
// ---------------------------------------------------------------------------
#define GSTG  3
#define TILEW 4096    // words per operand per stage (128 rows * 32 words)

__global__ void __launch_bounds__(256) gemm_f16(const float* __restrict__ bias_q,
                                                const float* __restrict__ bias_k,
                                                const float* __restrict__ bias_v,
                                                float* __restrict__ Cext,
                                                int mode)
{
    extern __shared__ uint32_t sm[];
    const uint32_t smb = smem_u32(sm);

    const int outmode = (mode >= 0) ? mode : (int)blockIdx.z;
    const float* bias = (outmode == 0) ? bias_q : (outmode == 1) ? bias_k
                       : (outmode == 2) ? bias_v : bias_q;

    const int t    = threadIdx.x;
    const int lane = t & 31;
    const int warp = t >> 5;
    const int wm   = warp & 3;
    const int wn   = warp >> 2;
    const int m0   = blockIdx.y * 128;
    const int n0   = blockIdx.x * 128;

    const uint32_t* A = (outmode == 3) ? g_attn16 : g_x16;
    const uint32_t* W = g_w16[outmode];

    float c[2][8][4];
#pragma unroll
    for (int mt = 0; mt < 2; mt++)
#pragma unroll
        for (int nt = 0; nt < 8; nt++)
#pragma unroll
            for (int i = 0; i < 4; i++) c[mt][nt][i] = 0.f;

    auto issue = [&](int s) {
        const int bufw = (s % GSTG) * 2 * TILEW;
#pragma unroll
        for (int i = 0; i < 4; i++) {
            const int idx = t + i * 256;          // 0..1023 chunks
            const int row = idx >> 3;
            const int c4  = idx & 7;
            const uint32_t sd = (uint32_t)(row * 128 + ((c4 ^ (row & 7)) << 4));
            cpa16s(smb + bufw * 4 + sd,           A + (size_t)(m0 + row) * KW + s * 32 + c4 * 4);
            cpa16s(smb + (bufw + TILEW) * 4 + sd, W + (size_t)(n0 + row) * KW + s * 32 + c4 * 4);
        }
        asm volatile("cp.async.commit_group;" ::: "memory");
    };

    const int NK = KD / 64;   // 16 stages
    issue(0); issue(1);

    for (int s = 0; s < NK; s++) {
        if (s == NK - 1) asm volatile("cp.async.wait_group 0;" ::: "memory");
        else             asm volatile("cp.async.wait_group 1;" ::: "memory");
        __syncthreads();
        if (s + 2 < NK) issue(s + 2);

        const uint32_t Ab = smb + (uint32_t)((s % GSTG) * 2 * TILEW) * 4;
        const uint32_t Wb = Ab + TILEW * 4;

#pragma unroll
        for (int ks = 0; ks < 4; ks++) {
            const int chunk = 2 * ks + (lane >> 4);
            uint32_t af[2][4], bf[8][2];
#pragma unroll
            for (int mt = 0; mt < 2; mt++) {
                const int row = wm * 32 + mt * 16 + (lane & 15);
                ldsm4(sw_addr(Ab, row, chunk), af[mt][0], af[mt][1], af[mt][2], af[mt][3]);
            }
#pragma unroll
            for (int ntp = 0; ntp < 4; ntp++) {
                const int row = wn * 64 + ntp * 16 + (lane & 15);
                uint32_t r0, r1, r2, r3;
                ldsm4(sw_addr(Wb, row, chunk), r0, r1, r2, r3);
                bf[2*ntp][0]   = r0; bf[2*ntp][1]   = r2;
                bf[2*ntp+1][0] = r1; bf[2*ntp+1][1] = r3;
            }
#pragma unroll
            for (int mt = 0; mt < 2; mt++)
#pragma unroll
                for (int nt = 0; nt < 8; nt++)
                    mma_f16(c[mt][nt], af[mt], bf[nt]);
        }
    }

    const int g  = lane >> 2;
    const int kq = lane & 3;

    if (outmode < 3) {
        uint32_t* dst = (outmode == 0) ? g_q16 : (outmode == 1) ? g_k16 : g_v16;
        const float qs = (outmode == 0) ? 0.18033688f : 1.f;   // 0.125 * log2(e)
#pragma unroll
        for (int mt = 0; mt < 2; mt++) {
            const int r0 = m0 + wm * 32 + mt * 16 + g;
#pragma unroll
            for (int nt = 0; nt < 8; nt++) {
                const int n  = n0 + wn * 64 + nt * 8 + (kq << 1);
                const float b0 = bias[n], b1 = bias[n + 1];
                const int h  = n >> 6;
                const int hw = (n & 63) >> 1;
#pragma unroll
                for (int half = 0; half < 2; half++) {
                    const int r = r0 + half * 8;
                    const int b = r >> 11;
                    const int s = r & (SS - 1);
                    const float v0 = (c[mt][nt][half * 2 + 0] + b0) * qs;
                    const float v1 = (c[mt][nt][half * 2 + 1] + b1) * qs;
                    dst[(((size_t)(b * HH + h)) * SS + s) * HDW + hw] = packh2(v0, v1);
                }
            }
        }
    } else {
#pragma unroll
        for (int mt = 0; mt < 2; mt++) {
            const int r0 = m0 + wm * 32 + mt * 16 + g;
#pragma unroll
            for (int nt = 0; nt < 8; nt++) {
                const int n  = n0 + wn * 64 + nt * 8 + (kq << 1);
                const float b0 = bias[n], b1 = bias[n + 1];
#pragma unroll
                for (int half = 0; half < 2; half++) {
                    const int r = r0 + half * 8;
                    float2* p = (float2*)&Cext[(size_t)r * DD + n];
                    *p = make_float2(c[mt][nt][half * 2 + 0] + b0,
                                     c[mt][nt][half * 2 + 1] + b1);
                }
            }
        }
    }
}

// ---------------------------------------------------------------------------
// FP16 tensor-core causal flash attention — SPLIT-KV halves.
// 256 thr = 8 warps. Warps 0-3 (half 0) process even kv tiles, warps 4-7
// (half 1) odd kv tiles, over the same 64 q-rows (16 rows per wq group).
// Max-free softmax makes partials combine by pure addition at the end.
// 4 smem tile regions: (pair parity) x (half), each K 8KB + V 8KB = 64KB.
// ---------------------------------------------------------------------------
__global__ void __launch_bounds__(256) attn_f16()
{
    extern __shared__ uint32_t sm[];   // 16384 words = 64 KB
    const uint32_t smb = smem_u32(sm);

    const int bh   = blockIdx.y;
    const int qt   = (gridDim.x - 1) - blockIdx.x;  // heavy tiles first
    const int tid  = threadIdx.x;
    const int lane = tid & 31;
    const int warp = tid >> 5;      // 0..7
    const int half = warp >> 2;     // kv parity this warp handles
    const int wq   = warp & 3;      // q-row group (16 rows)
    const int g    = lane >> 2;
    const int kq   = lane & 3;

    const uint32_t* Qw = g_q16 + (size_t)bh * SS * HDW;
    const uint32_t* Kw = g_k16 + (size_t)bh * SS * HDW;
    const uint32_t* Vw = g_v16 + (size_t)bh * SS * HDW;

    // ---- stage Q tile (64 x 32 words) into region 0, extract A-fragments ----
#pragma unroll
    for (int i = 0; i < 2; i++) {
        const int idx = tid + i * 256;       // 0..511 chunks
        const int row = idx >> 3;
        const int c4  = idx & 7;
        uint4 f = *(const uint4*)(Qw + ((size_t)qt * 64 + row) * HDW + c4 * 4);
        *(uint4*)(sm + row * 32 + ((c4 ^ (row & 7)) << 2)) = f;
    }
    __syncthreads();

    uint32_t qa[4][4];
#pragma unroll
    for (int ks = 0; ks < 4; ks++) {
        const int row   = wq * 16 + (lane & 15);
        const int chunk = 2 * ks + (lane >> 4);
        ldsm4(sw_addr(smb, row, chunk), qa[ks][0], qa[ks][1], qa[ks][2], qa[ks][3]);
    }
    __syncthreads();   // Q reads done before cp.async overwrites region 0

    const int NT = qt + 1;
    const int NP = (NT + 1) >> 1;

    // region r (0..3) = (pair parity)*2 + half; each 4096 words (K | V)
    auto issue_kv = [&](int kt, int region) {
        const uint32_t kb = smb + (uint32_t)region * 16384;   // bytes
#pragma unroll
        for (int i = 0; i < 2; i++) {
            const int idx = tid + i * 256;   // 0..511 chunks per tile
            const int row = idx >> 3;
            const int c4  = idx & 7;
            const uint32_t sd = (uint32_t)(row * 128 + ((c4 ^ (row & 7)) << 4));
            const size_t go = ((size_t)kt * 64 + row) * HDW + c4 * 4;
            cpa16s(kb + sd,        Kw + go);
            cpa16s(kb + 8192 + sd, Vw + go);
        }
    };
    auto issue_pair = [&](int p) {
#pragma unroll
        for (int h = 0; h < 2; h++) {
            const int kv = 2 * p + h;
            if (kv < NT) issue_kv(kv, ((p & 1) << 1) + h);
        }
        asm volatile("cp.async.commit_group;" ::: "memory");
    };

    issue_pair(0);

    float acc[8][4];
#pragma unroll
    for (int nt = 0; nt < 8; nt++)
#pragma unroll
        for (int i = 0; i < 4; i++) acc[nt][i] = 0.f;
    float lacc[4] = {0.f, 0.f, 0.f, 0.f};
    const uint32_t ones2[2] = {0x3C003C00u, 0x3C003C00u};

    const int rowg0 = qt * 64 + wq * 16 + g;
    const int rowg1 = rowg0 + 8;

    for (int p = 0; p < NP; p++) {
        asm volatile("cp.async.wait_group 0;" ::: "memory");
        __syncthreads();
        if (p + 1 < NP) issue_pair(p + 1);

        const int kv = 2 * p + half;
        if (kv >= NT) continue;   // only ever the last odd slot; post-barrier

        const uint32_t Kb = smb + (uint32_t)((((p & 1) << 1) + half) * 16384);
        const uint32_t Vb = Kb + 8192;

        // ---- S = Q @ K^T, fp16 accumulators ----
        uint32_t ch[8][2];
#pragma unroll
        for (int nt = 0; nt < 8; nt++) { ch[nt][0] = 0u; ch[nt][1] = 0u; }

#pragma unroll
        for (int ks = 0; ks < 4; ks++) {
            const int chunk = 2 * ks + (lane >> 4);
#pragma unroll
            for (int ntp = 0; ntp < 4; ntp++) {
                const int row = ntp * 16 + (lane & 15);
                uint32_t r0, r1, r2, r3;
                ldsm4(sw_addr(Kb, row, chunk), r0, r1, r2, r3);
                uint32_t kf0[2] = {r0, r2};
                uint32_t kf1[2] = {r1, r3};
                mma_f16h(ch[2*ntp],   qa[ks], kf0);
                mma_f16h(ch[2*ntp+1], qa[ks], kf1);
            }
        }

        // ---- causal mask in packed fp16 (diagonal tile only) ----
        if (kv == qt) {
#pragma unroll
            for (int nt = 0; nt < 8; nt++) {
                const int colb = kv * 64 + nt * 8 + (kq << 1);
                uint32_t v0 = ch[nt][0];
                if (colb     > rowg0) v0 = (v0 & 0xFFFF0000u) | 0x0000FC00u;
                if (colb + 1 > rowg0) v0 = (v0 & 0x0000FFFFu) | 0xFC000000u;
                ch[nt][0] = v0;
                uint32_t v1 = ch[nt][1];
                if (colb     > rowg1) v1 = (v1 & 0xFFFF0000u) | 0x0000FC00u;
                if (colb + 1 > rowg1) v1 = (v1 & 0x0000FFFFu) | 0xFC000000u;
                ch[nt][1] = v1;
            }
        }

        // ---- p = exp2(s) in place ----
#pragma unroll
        for (int nt = 0; nt < 8; nt++) {
            ch[nt][0] = hex22(ch[nt][0]);
            ch[nt][1] = hex22(ch[nt][1]);
        }

        // ---- O += P @ V ; l += P @ ones ----
#pragma unroll
        for (int ksp = 0; ksp < 4; ksp++) {
            uint32_t pa[4];
            pa[0] = ch[2*ksp][0];
            pa[1] = ch[2*ksp][1];
            pa[2] = ch[2*ksp+1][0];
            pa[3] = ch[2*ksp+1][1];
            mma_f16(lacc, pa, ones2);
#pragma unroll
            for (int ntp = 0; ntp < 4; ntp++) {
                const int row   = 16 * ksp + (lane & 15);
                const int chunk = 2 * ntp + (lane >> 4);
                uint32_t r0, r1, r2, r3;
                ldsm4t(sw_addr(Vb, row, chunk), r0, r1, r2, r3);
                uint32_t vb0[2] = {r0, r1};
                uint32_t vb1[2] = {r2, r3};
                mma_f16(acc[2*ntp],   pa, vb0);
                mma_f16(acc[2*ntp+1], pa, vb1);
            }
        }
    }

    // ---- combine halves (pure addition thanks to max-free softmax) ----
    __syncthreads();                 // all compute + buffer use done
    float* cs = (float*)sm;          // reuse tile smem; stride 35 (conflict-free)
    const int t2 = tid & 127;        // pairs tid <-> tid+128 (same wq, lane)
    if (half) {
        float* pp = cs + t2 * 35;
#pragma unroll
        for (int nt = 0; nt < 8; nt++)
#pragma unroll
            for (int i = 0; i < 4; i++) pp[nt * 4 + i] = acc[nt][i];
        pp[32] = lacc[0];
        pp[33] = lacc[2];
    }
    __syncthreads();
    if (!half) {
        float* pp = cs + t2 * 35;
#pragma unroll
        for (int nt = 0; nt < 8; nt++)
#pragma unroll
            for (int i = 0; i < 4; i++) acc[nt][i] += pp[nt * 4 + i];
        const float l0 = lacc[0] + pp[32];
        const float l1 = lacc[2] + pp[33];

        const int b = bh >> 4, h = bh & 15;
        const float inv0 = 1.f / l0;
        const float inv1 = 1.f / l1;
        const int qr0 = rowg0;
        const int qr1 = rowg1;
#pragma unroll
        for (int nt = 0; nt < 8; nt++) {
            const int word = h * 32 + nt * 4 + kq;
            g_attn16[((size_t)(b * SS + qr0)) * (DD/2) + word] =
                packh2(acc[nt][0] * inv0, acc[nt][1] * inv0);
            g_attn16[((size_t)(b * SS + qr1)) * (DD/2) + word] =
                packh2(acc[nt][2] * inv1, acc[nt][3] * inv1);
        }
    }
}

// ---------------------------------------------------------------------------
extern "C" void kernel_launch(void* const* d_in, const int* in_sizes, int n_in,
                              void* d_out, int out_size)
{
    const float* x  = (const float*)d_in[0];
    const float* qw = (const float*)d_in[1];
    const float* qb = (const float*)d_in[2];
    const float* kw = (const float*)d_in[3];
    const float* kb = (const float*)d_in[4];
    const float* vw = (const float*)d_in[5];
    const float* vb = (const float*)d_in[6];
    const float* ow = (const float*)d_in[7];
    const float* ob = (const float*)d_in[8];
    float* out = (float*)d_out;

    const int gemm_smem = GSTG * 2 * TILEW * (int)sizeof(uint32_t);  // 96 KB
    const int attn_smem = 16384 * (int)sizeof(uint32_t);             // 64 KB
    cudaFuncSetAttribute(gemm_f16, cudaFuncAttributeMaxDynamicSharedMemorySize, gemm_smem);
    cudaFuncSetAttribute(attn_f16, cudaFuncAttributeMaxDynamicSharedMemorySize, attn_smem);

    prep_f16<<<(MDIM + 4 * DD) * (KD / 8) / 256, 256>>>(x, qw, kw, vw, ow);

    // fused QKV: z selects outmode
    gemm_f16<<<dim3(DD / 128, MDIM / 128, 3), 256, gemm_smem>>>(qb, kb, vb, nullptr, -1);

    attn_f16<<<dim3(SS / 64, BB * HH), 256, attn_smem>>>();

    gemm_f16<<<dim3(DD / 128, MDIM / 128, 1), 256, gemm_smem>>>(ob, ob, ob, out, 3);
}

// round 16
// speedup vs baseline: 1.0235x; 1.0235x over previous
#include <cuda_runtime.h>
#include <cuda_fp16.h>
#include <cstdint>

// Problem constants: B=2, S=2048, D=1024, H=16, HD=64
#define BB   2
#define SS   2048
#define DD   1024
#define HH   16
#define HD   64
#define MDIM (BB*SS)     // 4096
#define KD   DD          // 1024
#define KW   (KD/2)      // 512 fp16x2 words per row
#define HDW  (HD/2)      // 32 words per head row

// Scratch (allocation-free rule). fp16x2 packed words, plain layouts.
__device__ uint32_t g_x16[MDIM*KW];
__device__ uint32_t g_w16[4][DD*KW];          // qw,kw,vw,ow
__device__ uint32_t g_q16[BB*HH*SS*HDW];      // [B,H,S,HD] (q pre-scaled by 0.125*log2e)
__device__ uint32_t g_k16[BB*HH*SS*HDW];
__device__ uint32_t g_v16[BB*HH*SS*HDW];
__device__ uint32_t g_attn16[BB*SS*DD/2];     // [B,S,D]

// ---------------------------------------------------------------------------
// helpers
// ---------------------------------------------------------------------------
__device__ __forceinline__ uint32_t packh2(float lo, float hi) {
    uint32_t r;
    asm("cvt.rn.f16x2.f32 %0, %1, %2;" : "=r"(r) : "f"(hi), "f"(lo));
    return r;   // low half = lo
}
__device__ __forceinline__ uint32_t hex22(uint32_t a) {
    uint32_t r; asm("ex2.approx.f16x2 %0,%1;" : "=r"(r) : "r"(a)); return r;
}

// fp32-accum MMA (PV + projections)
__device__ __forceinline__ void mma_f16(float* c, const uint32_t* a, const uint32_t* b) {
    asm volatile(
        "mma.sync.aligned.m16n8k16.row.col.f32.f16.f16.f32 "
        "{%0,%1,%2,%3}, {%4,%5,%6,%7}, {%8,%9}, {%0,%1,%2,%3};"
        : "+f"(c[0]), "+f"(c[1]), "+f"(c[2]), "+f"(c[3])
        : "r"(a[0]), "r"(a[1]), "r"(a[2]), "r"(a[3]),
          "r"(b[0]), "r"(b[1]));
}
// fp16-accum MMA (QK scores): C fragment = 2 packed h2 regs {c0,c1},{c2,c3}
__device__ __forceinline__ void mma_f16h(uint32_t* ch, const uint32_t* a, const uint32_t* b) {
    asm volatile(
        "mma.sync.aligned.m16n8k16.row.col.f16.f16.f16.f16 "
        "{%0,%1}, {%2,%3,%4,%5}, {%6,%7}, {%0,%1};"
        : "+r"(ch[0]), "+r"(ch[1])
        : "r"(a[0]), "r"(a[1]), "r"(a[2]), "r"(a[3]),
          "r"(b[0]), "r"(b[1]));
}

__device__ __forceinline__ void ldsm4(uint32_t addr, uint32_t& r0, uint32_t& r1,
                                      uint32_t& r2, uint32_t& r3) {
    asm volatile("ldmatrix.sync.aligned.m8n8.x4.shared.b16 {%0,%1,%2,%3}, [%4];"
                 : "=r"(r0), "=r"(r1), "=r"(r2), "=r"(r3) : "r"(addr));
}
__device__ __forceinline__ void ldsm4t(uint32_t addr, uint32_t& r0, uint32_t& r1,
                                       uint32_t& r2, uint32_t& r3) {
    asm volatile("ldmatrix.sync.aligned.m8n8.x4.trans.shared.b16 {%0,%1,%2,%3}, [%4];"
                 : "=r"(r0), "=r"(r1), "=r"(r2), "=r"(r3) : "r"(addr));
}

__device__ __forceinline__ void cpa16s(uint32_t saddr, const void* g) {
    asm volatile("cp.async.cg.shared.global [%0], [%1], 16;" :: "r"(saddr), "l"(g) : "memory");
}

__device__ __forceinline__ uint32_t smem_u32(const void* p) {
    uint32_t a;
    asm("{ .reg .u64 t; cvta.to.shared.u64 t, %1; cvt.u32.u64 %0, t; }" : "=r"(a) : "l"(p));
    return a;
}

// swizzled byte address of 16B chunk (row: 128B pitch, chunk 0..7)
__device__ __forceinline__ uint32_t sw_addr(uint32_t base, int row, int chunk) {
    return base + (uint32_t)(row * 128 + ((chunk ^ (row & 7)) << 4));
}

// ---------------------------------------------------------------------------
// prep: fp32 -> fp16x2 words. 8192 rows x 512 words (x then qw,kw,vw,ow).
// ---------------------------------------------------------------------------
__global__ void __launch_bounds__(256) prep_f16(const float* __restrict__ x,
                                                const float* __restrict__ qw,
                                                const float* __restrict__ kw,
                                                const float* __restrict__ vw,
                                                const float* __restrict__ ow)
{
    const int idx = blockIdx.x * 256 + threadIdx.x;
    const int row = idx >> 7;
    const int q8  = (idx & 127) << 3;

    const float* src;
    uint32_t*    dst;
    if (row < MDIM) {
        src = x + (size_t)row * KD;
        dst = g_x16 + (size_t)row * KW;
    } else {
        const int w = (row - MDIM) >> 10;
        const int r = (row - MDIM) & 1023;
        const float* ws = (w == 0) ? qw : (w == 1) ? kw : (w == 2) ? vw : ow;
        src = ws + (size_t)r * KD;
        dst = g_w16[w] + (size_t)r * KW;
    }
    float4 f0 = *(const float4*)(src + q8);
    float4 f1 = *(const float4*)(src + q8 + 4);
    uint4 o;
    o.x = packh2(f0.x, f0.y); o.y = packh2(f0.z, f0.w);
    o.z = packh2(f1.x, f1.y); o.w = packh2(f1.z, f1.w);
    *(uint4*)(dst + (q8 >> 1)) = o;
}

// ---------------------------------------------------------------------------
// FP16 tensor-core GEMM, CTA tile 128x64 for high occupancy (3 CTAs/SM,
// 24 warps/SM = 6 per SMSP): C = A @ W^T + bias.
// 256 thr = 8 warps (4m x 2n), warp tile 32x32.
// BK=64 halves/stage (128B rows, XOR-swizzled), 3-stage cp.async.
// smem/stage: A 128x32w (16KB) + B 64x32w (8KB) = 24KB; 3 stages = 72KB.
// ---------------------------------------------------------------------------
#define GSTG   3
#define STGW   6144   // words per stage (A 4096 + B 2048)

__global__ void __launch_bounds__(256, 3) gemm_f16(const float* __restrict__ bias_q,
                                                   const float* __restrict__ bias_k,
                                                   const float* __restrict__ bias_v,
                                                   float* __restrict__ Cext,
                                                   int mode)
{
    extern __shared__ uint32_t sm[];
    const uint32_t smb = smem_u32(sm);

    const int outmode = (mode >= 0) ? mode : (int)blockIdx.z;
    const float* bias = (outmode == 0) ? bias_q : (outmode == 1) ? bias_k
                       : (outmode == 2) ? bias_v : bias_q;

    const int t    = threadIdx.x;
    const int lane = t & 31;
    const int warp = t >> 5;
    const int wm   = warp & 3;            // 4 m-groups of 32 rows
    const int wn   = warp >> 2;           // 2 n-groups of 32 cols
    const int m0   = blockIdx.y * 128;
    const int n0   = blockIdx.x * 64;

    const uint32_t* A = (outmode == 3) ? g_attn16 : g_x16;
    const uint32_t* W = g_w16[outmode];

    float c[2][4][4];
#pragma unroll
    for (int mt = 0; mt < 2; mt++)
#pragma unroll
        for (int nt = 0; nt < 4; nt++)
#pragma unroll
            for (int i = 0; i < 4; i++) c[mt][nt][i] = 0.f;

    auto issue = [&](int s) {
        const int bufw = (s % GSTG) * STGW;
        // A tile: 128 rows -> 1024 chunks
#pragma unroll
        for (int i = 0; i < 4; i++) {
            const int idx = t + i * 256;
            const int row = idx >> 3;
            const int c4  = idx & 7;
            const uint32_t sd = (uint32_t)(row * 128 + ((c4 ^ (row & 7)) << 4));
            cpa16s(smb + bufw * 4 + sd, A + (size_t)(m0 + row) * KW + s * 32 + c4 * 4);
        }
        // B tile: 64 rows -> 512 chunks
#pragma unroll
        for (int i = 0; i < 2; i++) {
            const int idx = t + i * 256;
            const int row = idx >> 3;
            const int c4  = idx & 7;
            const uint32_t sd = (uint32_t)(row * 128 + ((c4 ^ (row & 7)) << 4));
            cpa16s(smb + (bufw + 4096) * 4 + sd, W + (size_t)(n0 + row) * KW + s * 32 + c4 * 4);
        }
        asm volatile("cp.async.commit_group;" ::: "memory");
    };

    const int NK = KD / 64;   // 16 stages
    issue(0); issue(1);

    for (int s = 0; s < NK; s++) {
        if (s == NK - 1) asm volatile("cp.async.wait_group 0;" ::: "memory");
        else             asm volatile("cp.async.wait_group 1;" ::: "memory");
        __syncthreads();
        if (s + 2 < NK) issue(s + 2);

        const uint32_t Ab = smb + (uint32_t)((s % GSTG) * STGW) * 4;
        const uint32_t Wb = Ab + 4096 * 4;

#pragma unroll
        for (int ks = 0; ks < 4; ks++) {
            const int chunk = 2 * ks + (lane >> 4);
            uint32_t af[2][4], bf[4][2];
#pragma unroll
            for (int mt = 0; mt < 2; mt++) {
                const int row = wm * 32 + mt * 16 + (lane & 15);
                ldsm4(sw_addr(Ab, row, chunk), af[mt][0], af[mt][1], af[mt][2], af[mt][3]);
            }
#pragma unroll
            for (int ntp = 0; ntp < 2; ntp++) {
                const int row = wn * 32 + ntp * 16 + (lane & 15);
                uint32_t r0, r1, r2, r3;
                ldsm4(sw_addr(Wb, row, chunk), r0, r1, r2, r3);
                bf[2*ntp][0]   = r0; bf[2*ntp][1]   = r2;
                bf[2*ntp+1][0] = r1; bf[2*ntp+1][1] = r3;
            }
#pragma unroll
            for (int mt = 0; mt < 2; mt++)
#pragma unroll
                for (int nt = 0; nt < 4; nt++)
                    mma_f16(c[mt][nt], af[mt], bf[nt]);
        }
    }

    const int g  = lane >> 2;
    const int kq = lane & 3;

    if (outmode < 3) {
        uint32_t* dst = (outmode == 0) ? g_q16 : (outmode == 1) ? g_k16 : g_v16;
        const float qs = (outmode == 0) ? 0.18033688f : 1.f;   // 0.125 * log2(e)
#pragma unroll
        for (int mt = 0; mt < 2; mt++) {
            const int r0 = m0 + wm * 32 + mt * 16 + g;
#pragma unroll
            for (int nt = 0; nt < 4; nt++) {
                const int n  = n0 + wn * 32 + nt * 8 + (kq << 1);
                const float b0 = bias[n], b1 = bias[n + 1];
                const int h  = n >> 6;
                const int hw = (n & 63) >> 1;
#pragma unroll
                for (int half = 0; half < 2; half++) {
                    const int r = r0 + half * 8;
                    const int b = r >> 11;
                    const int s = r & (SS - 1);
                    const float v0 = (c[mt][nt][half * 2 + 0] + b0) * qs;
                    const float v1 = (c[mt][nt][half * 2 + 1] + b1) * qs;
                    dst[(((size_t)(b * HH + h)) * SS + s) * HDW + hw] = packh2(v0, v1);
                }
            }
        }
    } else {
#pragma unroll
        for (int mt = 0; mt < 2; mt++) {
            const int r0 = m0 + wm * 32 + mt * 16 + g;
#pragma unroll
            for (int nt = 0; nt < 4; nt++) {
                const int n  = n0 + wn * 32 + nt * 8 + (kq << 1);
                const float b0 = bias[n], b1 = bias[n + 1];
#pragma unroll
                for (int half = 0; half < 2; half++) {
                    const int r = r0 + half * 8;
                    float2* p = (float2*)&Cext[(size_t)r * DD + n];
                    *p = make_float2(c[mt][nt][half * 2 + 0] + b0,
                                     c[mt][nt][half * 2 + 1] + b1);
                }
            }
        }
    }
}

// ---------------------------------------------------------------------------
// FP16 tensor-core causal flash attention (round-13 best version, verbatim).
// Max-free softmax, fp16-accum QK, l via ones-column MMA.
// Grid: (S/64, B*H). Block: 128 thr = 4 warps x 16 q-rows.
// ---------------------------------------------------------------------------
__global__ void __launch_bounds__(128) attn_f16()
{
    extern __shared__ uint32_t sm[];   // 2 bufs * (K 2048w | V 2048w) = 8192 words
    const uint32_t smb = smem_u32(sm);

    const int bh   = blockIdx.y;
    const int qt   = (gridDim.x - 1) - blockIdx.x;  // heavy tiles first
    const int tid  = threadIdx.x;
    const int lane = tid & 31;
    const int warp = tid >> 5;
    const int g    = lane >> 2;
    const int kq   = lane & 3;

    const uint32_t* Qw = g_q16 + (size_t)bh * SS * HDW;
    const uint32_t* Kw = g_k16 + (size_t)bh * SS * HDW;
    const uint32_t* Vw = g_v16 + (size_t)bh * SS * HDW;

    // ---- stage Q tile (64 x 32 words) into buf0, extract A-fragments ----
#pragma unroll
    for (int i = 0; i < 4; i++) {
        const int idx = tid + i * 128;       // 0..511 chunks
        const int row = idx >> 3;
        const int c4  = idx & 7;
        uint4 f = *(const uint4*)(Qw + ((size_t)qt * 64 + row) * HDW + c4 * 4);
        *(uint4*)(sm + row * 32 + ((c4 ^ (row & 7)) << 2)) = f;
    }
    __syncthreads();

    uint32_t qa[4][4];
#pragma unroll
    for (int ks = 0; ks < 4; ks++) {
        const int row   = warp * 16 + (lane & 15);
        const int chunk = 2 * ks + (lane >> 4);
        ldsm4(sw_addr(smb, row, chunk), qa[ks][0], qa[ks][1], qa[ks][2], qa[ks][3]);
    }
    __syncthreads();

    auto issue_kv = [&](int kt, int buf) {
        const uint32_t kb = smb + (uint32_t)buf * 16384;
#pragma unroll
        for (int i = 0; i < 4; i++) {
            const int idx = tid + i * 128;
            const int row = idx >> 3;
            const int c4  = idx & 7;
            const uint32_t sd = (uint32_t)(row * 128 + ((c4 ^ (row & 7)) << 4));
            const size_t go = ((size_t)kt * 64 + row) * HDW + c4 * 4;
            cpa16s(kb + sd,        Kw + go);
            cpa16s(kb + 8192 + sd, Vw + go);
        }
        asm volatile("cp.async.commit_group;" ::: "memory");
    };

    issue_kv(0, 0);

    float acc[8][4];
#pragma unroll
    for (int nt = 0; nt < 8; nt++)
#pragma unroll
        for (int i = 0; i < 4; i++) acc[nt][i] = 0.f;
    float lacc[4] = {0.f, 0.f, 0.f, 0.f};   // row sums via ones-column MMA
    const uint32_t ones2[2] = {0x3C003C00u, 0x3C003C00u};

    const int row0  = warp * 16 + g;
    const int rowg0 = qt * 64 + row0;
    const int rowg1 = rowg0 + 8;

    for (int kt = 0; kt <= qt; kt++) {
        asm volatile("cp.async.wait_group 0;" ::: "memory");
        __syncthreads();
        if (kt + 1 <= qt) issue_kv(kt + 1, (kt + 1) & 1);

        const uint32_t Kb = smb + (uint32_t)(kt & 1) * 16384;
        const uint32_t Vb = Kb + 8192;

        // ---- S = Q @ K^T, fp16 accumulators ----
        uint32_t ch[8][2];
#pragma unroll
        for (int nt = 0; nt < 8; nt++) { ch[nt][0] = 0u; ch[nt][1] = 0u; }

#pragma unroll
        for (int ks = 0; ks < 4; ks++) {
            const int chunk = 2 * ks + (lane >> 4);
#pragma unroll
            for (int ntp = 0; ntp < 4; ntp++) {
                const int row = ntp * 16 + (lane & 15);
                uint32_t r0, r1, r2, r3;
                ldsm4(sw_addr(Kb, row, chunk), r0, r1, r2, r3);
                uint32_t kf0[2] = {r0, r2};
                uint32_t kf1[2] = {r1, r3};
                mma_f16h(ch[2*ntp],   qa[ks], kf0);
                mma_f16h(ch[2*ntp+1], qa[ks], kf1);
            }
        }

        // ---- causal mask in packed fp16 (diagonal tile only) ----
        if (kt == qt) {
#pragma unroll
            for (int nt = 0; nt < 8; nt++) {
                const int colb = kt * 64 + nt * 8 + (kq << 1);
                uint32_t v0 = ch[nt][0];
                if (colb     > rowg0) v0 = (v0 & 0xFFFF0000u) | 0x0000FC00u;
                if (colb + 1 > rowg0) v0 = (v0 & 0x0000FFFFu) | 0xFC000000u;
                ch[nt][0] = v0;
                uint32_t v1 = ch[nt][1];
                if (colb     > rowg1) v1 = (v1 & 0xFFFF0000u) | 0x0000FC00u;
                if (colb + 1 > rowg1) v1 = (v1 & 0x0000FFFFu) | 0xFC000000u;
                ch[nt][1] = v1;
            }
        }

        // ---- p = exp2(s), in place: ch IS the PV A-fragment source ----
#pragma unroll
        for (int nt = 0; nt < 8; nt++) {
            ch[nt][0] = hex22(ch[nt][0]);
            ch[nt][1] = hex22(ch[nt][1]);
        }

        // ---- O += P @ V ; l += P @ ones ----
#pragma unroll
        for (int ksp = 0; ksp < 4; ksp++) {
            uint32_t pa[4];
            pa[0] = ch[2*ksp][0];
            pa[1] = ch[2*ksp][1];
            pa[2] = ch[2*ksp+1][0];
            pa[3] = ch[2*ksp+1][1];
            mma_f16(lacc, pa, ones2);
#pragma unroll
            for (int ntp = 0; ntp < 4; ntp++) {
                const int row   = 16 * ksp + (lane & 15);
                const int chunk = 2 * ntp + (lane >> 4);
                uint32_t r0, r1, r2, r3;
                ldsm4t(sw_addr(Vb, row, chunk), r0, r1, r2, r3);
                uint32_t vb0[2] = {r0, r1};
                uint32_t vb1[2] = {r2, r3};
                mma_f16(acc[2*ntp],   pa, vb0);
                mma_f16(acc[2*ntp+1], pa, vb1);
            }
        }
    }

    // ---- finalize: normalize, pack fp16, store [B,S,D] ----
    const int b = bh >> 4, h = bh & 15;
    const float inv0 = 1.f / lacc[0];
    const float inv1 = 1.f / lacc[2];
    const int qr0 = qt * 64 + row0;
    const int qr1 = qr0 + 8;
#pragma unroll
    for (int nt = 0; nt < 8; nt++) {
        const int word = h * 32 + nt * 4 + kq;
        g_attn16[((size_t)(b * SS + qr0)) * (DD/2) + word] =
            packh2(acc[nt][0] * inv0, acc[nt][1] * inv0);
        g_attn16[((size_t)(b * SS + qr1)) * (DD/2) + word] =
            packh2(acc[nt][2] * inv1, acc[nt][3] * inv1);
    }
}

// ---------------------------------------------------------------------------
extern "C" void kernel_launch(void* const* d_in, const int* in_sizes, int n_in,
                              void* d_out, int out_size)
{
    const float* x  = (const float*)d_in[0];
    const float* qw = (const float*)d_in[1];
    const float* qb = (const float*)d_in[2];
    const float* kw = (const float*)d_in[3];
    const float* kb = (const float*)d_in[4];
    const float* vw = (const float*)d_in[5];
    const float* vb = (const float*)d_in[6];
    const float* ow = (const float*)d_in[7];
    const float* ob = (const float*)d_in[8];
    float* out = (float*)d_out;

    const int gemm_smem = GSTG * STGW * (int)sizeof(uint32_t);   // 72 KB
    const int attn_smem = 8192 * (int)sizeof(uint32_t);          // 32 KB
    cudaFuncSetAttribute(gemm_f16, cudaFuncAttributeMaxDynamicSharedMemorySize, gemm_smem);

    prep_f16<<<(MDIM + 4 * DD) * (KD / 8) / 256, 256>>>(x, qw, kw, vw, ow);

    // fused QKV: z selects outmode
    gemm_f16<<<dim3(DD / 64, MDIM / 128, 3), 256, gemm_smem>>>(qb, kb, vb, nullptr, -1);

    attn_f16<<<dim3(SS / 64, BB * HH), 128, attn_smem>>>();

    gemm_f16<<<dim3(DD / 64, MDIM / 128, 1), 256, gemm_smem>>>(ob, ob, ob, out, 3);
}